// round 14
// baseline (speedup 1.0000x reference)
#include <cuda_runtime.h>
#include <cstdint>
#include <cstddef>

#define SEQ  4096
#define HID  1024
#define G4   4096
#define NCTA 128
#define SCAN_THREADS 256

typedef unsigned long long ull;

// ---------------- persistent device scratch (static: allocation-free) ----------
__device__ float g_xg[(size_t)SEQ * G4];   // 64 MB: precomputed input-side gates
// Tagged h records: (h value, tag) packed in 8B -> single-copy atomic.
// Record for h^{(s)} (state consumed at step s) lives in slot s&1 with tag s+1.
__device__ __align__(16) uint2 g_hrec[2][HID];   // 16 KB

// ---------------- packed f32x2 helpers ----------------------------------------
__device__ __forceinline__ ull pk2(float x, float y) {
  ull r; asm("mov.b64 %0, {%1, %2};" : "=l"(r) : "f"(x), "f"(y)); return r;
}
__device__ __forceinline__ void upk2(ull v, float& x, float& y) {
  asm("mov.b64 {%0, %1}, %2;" : "=f"(x), "=f"(y) : "l"(v));
}
__device__ __forceinline__ void fma2(ull& d, ull a, ull b) {
  asm("fma.rn.f32x2 %0, %1, %2, %0;" : "+l"(d) : "l"(a), "l"(b));
}

__device__ __forceinline__ float sigm(float x) {
  return __fdividef(1.0f, 1.0f + __expf(-x));
}
__device__ __forceinline__ float tanh_(float x) {
  float e = __expf(2.0f * x);
  return 1.0f - __fdividef(2.0f, e + 1.0f);
}

// strong (L2-coherent) 16B load: returns 2 records (h,tag,h,tag)
__device__ __forceinline__ uint4 ld_rec2(const uint2* p) {
  uint4 v;
  asm volatile("ld.relaxed.gpu.global.v4.b32 {%0,%1,%2,%3}, [%4];"
               : "=r"(v.x), "=r"(v.y), "=r"(v.z), "=r"(v.w) : "l"(p) : "memory");
  return v;
}
// strong 8B store: one record (h, tag) — tag travels with the payload
__device__ __forceinline__ void st_rec(uint2* p, float h, unsigned tag) {
  asm volatile("st.relaxed.gpu.global.v2.b32 [%0], {%1,%2};"
               :: "l"(p), "r"(__float_as_uint(h)), "r"(tag) : "memory");
}

// ==============================================================================
// Kernel 1: xg[m][n] = sum_k emb[inputs[m]][k] * W_ih[n][k] + b_ih[n] + b_hh[n]
// 128x128 tile, BK=8, 256 threads, 8x8 micro-tile via fma.rn.f32x2, 1-deep
// register prefetch pipeline. Block (0,0) also seeds the scan's h records:
// slot 0 = (h0, tag 1), slot 1 = zeros (stream-ordered before the scan).
// ==============================================================================
__global__ __launch_bounds__(256, 2) void xg_gemm(
    const int*   __restrict__ inputs,
    const float* __restrict__ emb,
    const float* __restrict__ Wih,
    const float* __restrict__ b_ih,
    const float* __restrict__ b_hh,
    const float* __restrict__ h0)
{
  if (blockIdx.x == 0 && blockIdx.y == 0) {
    for (int i = threadIdx.x; i < HID; i += 256) {
      g_hrec[0][i] = make_uint2(__float_as_uint(h0[i]), 1u);  // h^{(0)}, tag 1
      g_hrec[1][i] = make_uint2(0u, 0u);
    }
  }

  __shared__ __align__(16) float As[8][128];
  __shared__ __align__(16) float Bs[8][128];
  __shared__ int idx[128];

  const int tid = threadIdx.x;
  const int m0 = blockIdx.y << 7;
  const int n0 = blockIdx.x << 7;

  if (tid < 128) idx[tid] = inputs[m0 + tid];
  __syncthreads();

  const int lr = tid >> 1;           // 0..127 row for cooperative loads
  const int lk = (tid & 1) << 2;     // k offset 0 or 4
  const int tx = tid & 15;           // micro-tile col group
  const int ty = tid >> 4;           // micro-tile row group

  const float* aptr = emb + (size_t)idx[lr] * 1024 + lk;
  const float* bptr = Wih + (size_t)(n0 + lr) * 1024 + lk;

  ull acc2[8][4];
  #pragma unroll
  for (int i = 0; i < 8; ++i)
    #pragma unroll
    for (int p = 0; p < 4; ++p) acc2[i][p] = 0ULL;

  float4 av = *(const float4*)(aptr);
  float4 bv = *(const float4*)(bptr);

  for (int k0 = 0; k0 < 1024; k0 += 8) {
    __syncthreads();
    As[lk + 0][lr] = av.x; As[lk + 1][lr] = av.y;
    As[lk + 2][lr] = av.z; As[lk + 3][lr] = av.w;
    Bs[lk + 0][lr] = bv.x; Bs[lk + 1][lr] = bv.y;
    Bs[lk + 2][lr] = bv.z; Bs[lk + 3][lr] = bv.w;
    __syncthreads();

    const int kn = (k0 + 8 < 1024) ? (k0 + 8) : 0;
    av = *(const float4*)(aptr + kn);
    bv = *(const float4*)(bptr + kn);

    #pragma unroll
    for (int kk = 0; kk < 8; ++kk) {
      float4 a0 = *(const float4*)&As[kk][ty << 3];
      float4 a1 = *(const float4*)&As[kk][(ty << 3) + 4];
      float4 b0 = *(const float4*)&Bs[kk][tx << 3];
      float4 b1 = *(const float4*)&Bs[kk][(tx << 3) + 4];
      ull bq[4];
      bq[0] = pk2(b0.x, b0.y); bq[1] = pk2(b0.z, b0.w);
      bq[2] = pk2(b1.x, b1.y); bq[3] = pk2(b1.z, b1.w);
      float a[8] = {a0.x, a0.y, a0.z, a0.w, a1.x, a1.y, a1.z, a1.w};
      #pragma unroll
      for (int i = 0; i < 8; ++i) {
        ull ad = pk2(a[i], a[i]);
        #pragma unroll
        for (int p = 0; p < 4; ++p) fma2(acc2[i][p], ad, bq[p]);
      }
    }
  }

  float bias[8];
  #pragma unroll
  for (int p = 0; p < 8; ++p) {
    int n = n0 + (tx << 3) + p;
    bias[p] = b_ih[n] + b_hh[n];
  }
  #pragma unroll
  for (int i = 0; i < 8; ++i) {
    float c[8];
    #pragma unroll
    for (int p = 0; p < 4; ++p) upk2(acc2[i][p], c[2 * p], c[2 * p + 1]);
    #pragma unroll
    for (int p = 0; p < 8; ++p) c[p] += bias[p];
    int m = m0 + (ty << 3) + i;
    float* outp = g_xg + (size_t)m * G4 + n0 + (tx << 3);
    *(float4*)(outp)     = make_float4(c[0], c[1], c[2], c[3]);
    *(float4*)(outp + 4) = make_float4(c[4], c[5], c[6], c[7]);
  }
}

// ==============================================================================
// Kernel 2: persistent LSTM scan — R7 base with specialized polling.
// 128 CTAs x 256 threads; CTA b owns h columns [8b, 8b+8), warp w -> column j.
//
// Fill phase: ONLY warps 0-3 poll (128 threads x 8 records). All four 16B
// loads are issued up front (MLP=4 -> one-RT detection), then verified with
// independent spins that re-issue only the missing load. Warps 4-7 go straight
// to the barrier — their SMSPs are quiet during the wait. This halves chip
// poll traffic vs R7 and removes R7's two serial spin round trips, while
// keeping all spinning inside the barrier-throttled window (R11 lesson:
// unthrottled polling costs ~4 ms; R13 lesson: re-issue volume costs ~2 ms).
// ==============================================================================
__global__ __launch_bounds__(SCAN_THREADS, 1) void lstm_scan(
    const float* __restrict__ W_hh,
    const float* __restrict__ c0)
{
  const int tid  = threadIdx.x;
  const int lane = tid & 31;
  const int w    = tid >> 5;                  // warp 0..7
  const int j    = (blockIdx.x << 3) + w;     // 0..1023

  __shared__ __align__(16) float sh_h[HID];

  // load this thread's 128 weights (as 64 f32x2 pairs) into registers
  ull wreg[4][16];
  #pragma unroll
  for (int g = 0; g < 4; ++g) {
    const float* wp = W_hh + (size_t)(j + (g << 10)) * HID;
    #pragma unroll
    for (int i = 0; i < 16; ++i) {
      float2 v = *(const float2*)(wp + 2 * (lane + 32 * i));
      wreg[g][i] = pk2(v.x, v.y);
    }
  }
  float c = c0[j];   // replicated across lanes (identical updates keep it consistent)

  for (int s = 0; s < SEQ; ++s) {
    const unsigned need = (unsigned)s + 1u;        // tag of h^{(s)}
    const int par = s & 1;

    // prefetch this step's input-side gate values (long-scoreboard load,
    // overlaps the record polling below)
    float xgv = 0.0f;
    if (lane < 4) xgv = __ldg(g_xg + (size_t)s * G4 + j + (lane << 10));

    // --- fill: warps 0-3 poll 8 records each; issue-ahead, verify per-load ---
    if (w < 4) {
      const uint2* rp = &g_hrec[par][tid << 3];   // records 8*tid .. 8*tid+7
      uint4 r0 = ld_rec2(rp);
      uint4 r1 = ld_rec2(rp + 2);
      uint4 r2 = ld_rec2(rp + 4);
      uint4 r3 = ld_rec2(rp + 6);
      while (r0.y < need || r0.w < need) r0 = ld_rec2(rp);
      while (r1.y < need || r1.w < need) r1 = ld_rec2(rp + 2);
      while (r2.y < need || r2.w < need) r2 = ld_rec2(rp + 4);
      while (r3.y < need || r3.w < need) r3 = ld_rec2(rp + 6);
      float4* dst = (float4*)(sh_h + (tid << 3));
      dst[0] = make_float4(__uint_as_float(r0.x), __uint_as_float(r0.z),
                           __uint_as_float(r1.x), __uint_as_float(r1.z));
      dst[1] = make_float4(__uint_as_float(r2.x), __uint_as_float(r2.z),
                           __uint_as_float(r3.x), __uint_as_float(r3.z));
    }
    __syncthreads();

    // --- 4 dot products of length 1024, f32x2 packed, LDS.64 per chunk ---
    ull acc2[4];
    #pragma unroll
    for (int g = 0; g < 4; ++g) acc2[g] = 0ULL;
    #pragma unroll
    for (int i = 0; i < 16; ++i) {
      ull hh = *(const ull*)(sh_h + 2 * (lane + 32 * i));
      #pragma unroll
      for (int g = 0; g < 4; ++g) fma2(acc2[g], wreg[g][i], hh);
    }
    float acc[4];
    #pragma unroll
    for (int g = 0; g < 4; ++g) {
      float lo, hi; upk2(acc2[g], lo, hi);
      acc[g] = lo + hi;
    }
    // butterfly reduce: every lane ends with the full sums
    #pragma unroll
    for (int off = 16; off > 0; off >>= 1)
      #pragma unroll
      for (int g = 0; g < 4; ++g)
        acc[g] += __shfl_xor_sync(0xffffffffu, acc[g], off);

    float xg0 = __shfl_sync(0xffffffffu, xgv, 0);
    float xg1 = __shfl_sync(0xffffffffu, xgv, 1);
    float xg2 = __shfl_sync(0xffffffffu, xgv, 2);
    float xg3 = __shfl_sync(0xffffffffu, xgv, 3);

    // gate order i, f, g, o (PyTorch)
    float iv = sigm(acc[0] + xg0);
    float fv = sigm(acc[1] + xg1);
    float gv = tanh_(acc[2] + xg2);
    float ov = sigm(acc[3] + xg3);
    c = fv * c + iv * gv;
    float hn = ov * tanh_(c);

    // publish h^{(s+1)}: slot (s+1)&1, tag s+2
    if (lane == 0)
      st_rec(&g_hrec[(s + 1) & 1][j], hn, (unsigned)s + 2u);

    // keep next step's spinning inside the barrier-throttled window, and
    // protect sh_h against the next fill while warps still read it
    __syncthreads();
  }
}

// ==============================================================================
// Kernel 3: log_softmax over the final hidden state. h^{(4096)} sits in
// g_hrec[0][j].x (tag 4097). One CTA, 1024 threads.
// ==============================================================================
__global__ void lsm_kernel(float* __restrict__ out)
{
  const int tid  = threadIdx.x;
  const int lane = tid & 31;
  const int w    = tid >> 5;
  __shared__ float red[32];
  __shared__ float bcast[2];

  float v = __uint_as_float(g_hrec[0][tid].x);

  float m = v;
  #pragma unroll
  for (int o = 16; o > 0; o >>= 1) m = fmaxf(m, __shfl_xor_sync(0xffffffffu, m, o));
  if (lane == 0) red[w] = m;
  __syncthreads();
  if (tid < 32) {
    float x = red[tid];
    #pragma unroll
    for (int o = 16; o > 0; o >>= 1) x = fmaxf(x, __shfl_xor_sync(0xffffffffu, x, o));
    if (tid == 0) bcast[0] = x;
  }
  __syncthreads();
  m = bcast[0];

  float e = __expf(v - m);
  float s = e;
  #pragma unroll
  for (int o = 16; o > 0; o >>= 1) s += __shfl_xor_sync(0xffffffffu, s, o);
  if (lane == 0) red[w] = s;
  __syncthreads();
  if (tid < 32) {
    float x = red[tid];
    #pragma unroll
    for (int o = 16; o > 0; o >>= 1) x += __shfl_xor_sync(0xffffffffu, x, o);
    if (tid == 0) bcast[1] = logf(x);
  }
  __syncthreads();

  out[tid] = (v - m) - bcast[1];
}

// ==============================================================================
extern "C" void kernel_launch(void* const* d_in, const int* in_sizes, int n_in,
                              void* d_out, int out_size)
{
  const int*   inputs = (const int*)  d_in[0];
  const float* emb    = (const float*)d_in[1];
  const float* W_ih   = (const float*)d_in[2];
  const float* W_hh   = (const float*)d_in[3];
  const float* b_ih   = (const float*)d_in[4];
  const float* b_hh   = (const float*)d_in[5];
  const float* h0     = (const float*)d_in[6];
  const float* c0     = (const float*)d_in[7];
  float* out = (float*)d_out;

  dim3 grid(G4 / 128, SEQ / 128);
  xg_gemm<<<grid, 256>>>(inputs, emb, W_ih, b_ih, b_hh, h0);
  lstm_scan<<<NCTA, SCAN_THREADS>>>(W_hh, c0);
  lsm_kernel<<<1, HID>>>(out);
}

// round 15
// speedup vs baseline: 1.3098x; 1.3098x over previous
#include <cuda_runtime.h>
#include <cstdint>
#include <cstddef>

#define SEQ  4096
#define HID  1024
#define G4   4096
#define NCTA 128
#define SCAN_THREADS 256

typedef unsigned long long ull;

// ---------------- persistent device scratch (static: allocation-free) ----------
__device__ float g_xg[(size_t)SEQ * G4];   // 64 MB: precomputed input-side gates
// Tagged h records: (h value, tag) packed in 8B -> single-copy atomic.
// Record for h^{(s)} (state consumed at step s) lives in slot s&1 with tag s+1.
__device__ __align__(16) uint2 g_hrec[2][HID];   // 16 KB

// ---------------- packed f32x2 helpers ----------------------------------------
__device__ __forceinline__ ull pk2(float x, float y) {
  ull r; asm("mov.b64 %0, {%1, %2};" : "=l"(r) : "f"(x), "f"(y)); return r;
}
__device__ __forceinline__ void upk2(ull v, float& x, float& y) {
  asm("mov.b64 {%0, %1}, %2;" : "=f"(x), "=f"(y) : "l"(v));
}
__device__ __forceinline__ void fma2(ull& d, ull a, ull b) {
  asm("fma.rn.f32x2 %0, %1, %2, %0;" : "+l"(d) : "l"(a), "l"(b));
}

__device__ __forceinline__ float sigm(float x) {
  return __fdividef(1.0f, 1.0f + __expf(-x));
}
__device__ __forceinline__ float tanh_(float x) {
  float e = __expf(2.0f * x);
  return 1.0f - __fdividef(2.0f, e + 1.0f);
}

// strong (L2-coherent) 16B load: returns 2 records (h,tag,h,tag)
__device__ __forceinline__ uint4 ld_rec2(const uint2* p) {
  uint4 v;
  asm volatile("ld.relaxed.gpu.global.v4.b32 {%0,%1,%2,%3}, [%4];"
               : "=r"(v.x), "=r"(v.y), "=r"(v.z), "=r"(v.w) : "l"(p) : "memory");
  return v;
}
// strong 8B store: one record (h, tag) — tag travels with the payload
__device__ __forceinline__ void st_rec(uint2* p, float h, unsigned tag) {
  asm volatile("st.relaxed.gpu.global.v2.b32 [%0], {%1,%2};"
               :: "l"(p), "r"(__float_as_uint(h)), "r"(tag) : "memory");
}

// ==============================================================================
// Kernel 1: xg[m][n] = sum_k emb[inputs[m]][k] * W_ih[n][k] + b_ih[n] + b_hh[n]
// 128x128 tile, BK=8, 256 threads, 8x8 micro-tile via fma.rn.f32x2, 1-deep
// register prefetch pipeline. Block (0,0) also seeds the scan's h records:
// slot 0 = (h0, tag 1), slot 1 = zeros (stream-ordered before the scan).
// ==============================================================================
__global__ __launch_bounds__(256, 2) void xg_gemm(
    const int*   __restrict__ inputs,
    const float* __restrict__ emb,
    const float* __restrict__ Wih,
    const float* __restrict__ b_ih,
    const float* __restrict__ b_hh,
    const float* __restrict__ h0)
{
  if (blockIdx.x == 0 && blockIdx.y == 0) {
    for (int i = threadIdx.x; i < HID; i += 256) {
      g_hrec[0][i] = make_uint2(__float_as_uint(h0[i]), 1u);  // h^{(0)}, tag 1
      g_hrec[1][i] = make_uint2(0u, 0u);
    }
  }

  __shared__ __align__(16) float As[8][128];
  __shared__ __align__(16) float Bs[8][128];
  __shared__ int idx[128];

  const int tid = threadIdx.x;
  const int m0 = blockIdx.y << 7;
  const int n0 = blockIdx.x << 7;

  if (tid < 128) idx[tid] = inputs[m0 + tid];
  __syncthreads();

  const int lr = tid >> 1;           // 0..127 row for cooperative loads
  const int lk = (tid & 1) << 2;     // k offset 0 or 4
  const int tx = tid & 15;           // micro-tile col group
  const int ty = tid >> 4;           // micro-tile row group

  const float* aptr = emb + (size_t)idx[lr] * 1024 + lk;
  const float* bptr = Wih + (size_t)(n0 + lr) * 1024 + lk;

  ull acc2[8][4];
  #pragma unroll
  for (int i = 0; i < 8; ++i)
    #pragma unroll
    for (int p = 0; p < 4; ++p) acc2[i][p] = 0ULL;

  float4 av = *(const float4*)(aptr);
  float4 bv = *(const float4*)(bptr);

  for (int k0 = 0; k0 < 1024; k0 += 8) {
    __syncthreads();
    As[lk + 0][lr] = av.x; As[lk + 1][lr] = av.y;
    As[lk + 2][lr] = av.z; As[lk + 3][lr] = av.w;
    Bs[lk + 0][lr] = bv.x; Bs[lk + 1][lr] = bv.y;
    Bs[lk + 2][lr] = bv.z; Bs[lk + 3][lr] = bv.w;
    __syncthreads();

    const int kn = (k0 + 8 < 1024) ? (k0 + 8) : 0;
    av = *(const float4*)(aptr + kn);
    bv = *(const float4*)(bptr + kn);

    #pragma unroll
    for (int kk = 0; kk < 8; ++kk) {
      float4 a0 = *(const float4*)&As[kk][ty << 3];
      float4 a1 = *(const float4*)&As[kk][(ty << 3) + 4];
      float4 b0 = *(const float4*)&Bs[kk][tx << 3];
      float4 b1 = *(const float4*)&Bs[kk][(tx << 3) + 4];
      ull bq[4];
      bq[0] = pk2(b0.x, b0.y); bq[1] = pk2(b0.z, b0.w);
      bq[2] = pk2(b1.x, b1.y); bq[3] = pk2(b1.z, b1.w);
      float a[8] = {a0.x, a0.y, a0.z, a0.w, a1.x, a1.y, a1.z, a1.w};
      #pragma unroll
      for (int i = 0; i < 8; ++i) {
        ull ad = pk2(a[i], a[i]);
        #pragma unroll
        for (int p = 0; p < 4; ++p) fma2(acc2[i][p], ad, bq[p]);
      }
    }
  }

  float bias[8];
  #pragma unroll
  for (int p = 0; p < 8; ++p) {
    int n = n0 + (tx << 3) + p;
    bias[p] = b_ih[n] + b_hh[n];
  }
  #pragma unroll
  for (int i = 0; i < 8; ++i) {
    float c[8];
    #pragma unroll
    for (int p = 0; p < 4; ++p) upk2(acc2[i][p], c[2 * p], c[2 * p + 1]);
    #pragma unroll
    for (int p = 0; p < 8; ++p) c[p] += bias[p];
    int m = m0 + (ty << 3) + i;
    float* outp = g_xg + (size_t)m * G4 + n0 + (tx << 3);
    *(float4*)(outp)     = make_float4(c[0], c[1], c[2], c[3]);
    *(float4*)(outp + 4) = make_float4(c[4], c[5], c[6], c[7]);
  }
}

// ==============================================================================
// Kernel 2: persistent LSTM scan — exact R7 (6943us) base; the ONLY change is
// the poll loop: concurrent verification of both 16B record loads, each
// re-issued ONLY while not yet ready. This gives 1-RT detection (R13's
// strength) at R7's 1x steady re-issue traffic (R13 re-issued ready records:
// +2ms; R14 verified serially with stale loads: +3.6ms).
// 128 CTAs x 256 threads; CTA b owns h columns [8b, 8b+8), warp w -> column j.
// ==============================================================================
__global__ __launch_bounds__(SCAN_THREADS, 1) void lstm_scan(
    const float* __restrict__ W_hh,
    const float* __restrict__ c0)
{
  const int tid  = threadIdx.x;
  const int lane = tid & 31;
  const int w    = tid >> 5;                  // warp 0..7
  const int j    = (blockIdx.x << 3) + w;     // 0..1023

  __shared__ __align__(16) float sh_h[HID];

  // load this thread's 128 weights (as 64 f32x2 pairs) into registers
  ull wreg[4][16];
  #pragma unroll
  for (int g = 0; g < 4; ++g) {
    const float* wp = W_hh + (size_t)(j + (g << 10)) * HID;
    #pragma unroll
    for (int i = 0; i < 16; ++i) {
      float2 v = *(const float2*)(wp + 2 * (lane + 32 * i));
      wreg[g][i] = pk2(v.x, v.y);
    }
  }
  float c = c0[j];   // replicated across lanes (identical updates keep it consistent)

  for (int s = 0; s < SEQ; ++s) {
    const unsigned need = (unsigned)s + 1u;        // tag of h^{(s)}
    const int par = s & 1;

    // prefetch this step's input-side gate values (long-scoreboard load,
    // overlaps the record polling below)
    float xgv = 0.0f;
    if (lane < 4) xgv = __ldg(g_xg + (size_t)s * G4 + j + (lane << 10));

    // --- fill: poll own 4 records; concurrent verify, no redundant re-issue ---
    {
      const uint2* rp = &g_hrec[par][tid << 2];
      uint4 a = ld_rec2(rp);
      uint4 b = ld_rec2(rp + 2);
      bool ra = (a.y >= need) && (a.w >= need);
      bool rb = (b.y >= need) && (b.w >= need);
      while (!ra || !rb) {
        if (!ra) { a = ld_rec2(rp);     ra = (a.y >= need) && (a.w >= need); }
        if (!rb) { b = ld_rec2(rp + 2); rb = (b.y >= need) && (b.w >= need); }
      }
      // payloads only into smem (tags stripped) — one STS.128
      ((float4*)sh_h)[tid] =
          make_float4(__uint_as_float(a.x), __uint_as_float(a.z),
                      __uint_as_float(b.x), __uint_as_float(b.z));
    }
    __syncthreads();

    // --- 4 dot products of length 1024, f32x2 packed, LDS.64 per chunk ---
    ull acc2[4];
    #pragma unroll
    for (int g = 0; g < 4; ++g) acc2[g] = 0ULL;
    #pragma unroll
    for (int i = 0; i < 16; ++i) {
      ull hh = *(const ull*)(sh_h + 2 * (lane + 32 * i));
      #pragma unroll
      for (int g = 0; g < 4; ++g) fma2(acc2[g], wreg[g][i], hh);
    }
    float acc[4];
    #pragma unroll
    for (int g = 0; g < 4; ++g) {
      float lo, hi; upk2(acc2[g], lo, hi);
      acc[g] = lo + hi;
    }
    // butterfly reduce: every lane ends with the full sums
    #pragma unroll
    for (int off = 16; off > 0; off >>= 1)
      #pragma unroll
      for (int g = 0; g < 4; ++g)
        acc[g] += __shfl_xor_sync(0xffffffffu, acc[g], off);

    float xg0 = __shfl_sync(0xffffffffu, xgv, 0);
    float xg1 = __shfl_sync(0xffffffffu, xgv, 1);
    float xg2 = __shfl_sync(0xffffffffu, xgv, 2);
    float xg3 = __shfl_sync(0xffffffffu, xgv, 3);

    // gate order i, f, g, o (PyTorch)
    float iv = sigm(acc[0] + xg0);
    float fv = sigm(acc[1] + xg1);
    float gv = tanh_(acc[2] + xg2);
    float ov = sigm(acc[3] + xg3);
    c = fv * c + iv * gv;
    float hn = ov * tanh_(c);

    // publish h^{(s+1)}: slot (s+1)&1, tag s+2
    if (lane == 0)
      st_rec(&g_hrec[(s + 1) & 1][j], hn, (unsigned)s + 2u);

    // keep next step's spinning inside the barrier-throttled window, and
    // protect sh_h against the next fill while warps still read it
    __syncthreads();
  }
}

// ==============================================================================
// Kernel 3: log_softmax over the final hidden state. h^{(4096)} sits in
// g_hrec[0][j].x (tag 4097). One CTA, 1024 threads.
// ==============================================================================
__global__ void lsm_kernel(float* __restrict__ out)
{
  const int tid  = threadIdx.x;
  const int lane = tid & 31;
  const int w    = tid >> 5;
  __shared__ float red[32];
  __shared__ float bcast[2];

  float v = __uint_as_float(g_hrec[0][tid].x);

  float m = v;
  #pragma unroll
  for (int o = 16; o > 0; o >>= 1) m = fmaxf(m, __shfl_xor_sync(0xffffffffu, m, o));
  if (lane == 0) red[w] = m;
  __syncthreads();
  if (tid < 32) {
    float x = red[tid];
    #pragma unroll
    for (int o = 16; o > 0; o >>= 1) x = fmaxf(x, __shfl_xor_sync(0xffffffffu, x, o));
    if (tid == 0) bcast[0] = x;
  }
  __syncthreads();
  m = bcast[0];

  float e = __expf(v - m);
  float s = e;
  #pragma unroll
  for (int o = 16; o > 0; o >>= 1) s += __shfl_xor_sync(0xffffffffu, s, o);
  if (lane == 0) red[w] = s;
  __syncthreads();
  if (tid < 32) {
    float x = red[tid];
    #pragma unroll
    for (int o = 16; o > 0; o >>= 1) x += __shfl_xor_sync(0xffffffffu, x, o);
    if (tid == 0) bcast[1] = logf(x);
  }
  __syncthreads();

  out[tid] = (v - m) - bcast[1];
}

// ==============================================================================
extern "C" void kernel_launch(void* const* d_in, const int* in_sizes, int n_in,
                              void* d_out, int out_size)
{
  const int*   inputs = (const int*)  d_in[0];
  const float* emb    = (const float*)d_in[1];
  const float* W_ih   = (const float*)d_in[2];
  const float* W_hh   = (const float*)d_in[3];
  const float* b_ih   = (const float*)d_in[4];
  const float* b_hh   = (const float*)d_in[5];
  const float* h0     = (const float*)d_in[6];
  const float* c0     = (const float*)d_in[7];
  float* out = (float*)d_out;

  dim3 grid(G4 / 128, SEQ / 128);
  xg_gemm<<<grid, 256>>>(inputs, emb, W_ih, b_ih, b_hh, h0);
  lstm_scan<<<NCTA, SCAN_THREADS>>>(W_hh, c0);
  lsm_kernel<<<1, HID>>>(out);
}

// round 16
// speedup vs baseline: 1.4994x; 1.1447x over previous
#include <cuda_runtime.h>
#include <cstdint>
#include <cstddef>

#define SEQ  4096
#define HID  1024
#define G4   4096
#define NCTA 128
#define SCAN_THREADS 256

typedef unsigned long long ull;

// ---------------- persistent device scratch (static: allocation-free) ----------
__device__ float g_xg[(size_t)SEQ * G4];   // 64 MB: precomputed input-side gates
// Tagged h records: (h value, tag) packed in 8B -> single-copy atomic.
// Double-buffered by step parity. Consumers read 16B (2 records) at a time.
__device__ __align__(16) uint2 g_hrec[2][HID];   // 16 KB

// ---------------- packed f32x2 helpers ----------------------------------------
__device__ __forceinline__ ull pk2(float x, float y) {
  ull r; asm("mov.b64 %0, {%1, %2};" : "=l"(r) : "f"(x), "f"(y)); return r;
}
__device__ __forceinline__ void upk2(ull v, float& x, float& y) {
  asm("mov.b64 {%0, %1}, %2;" : "=f"(x), "=f"(y) : "l"(v));
}
__device__ __forceinline__ void fma2(ull& d, ull a, ull b) {
  asm("fma.rn.f32x2 %0, %1, %2, %0;" : "+l"(d) : "l"(a), "l"(b));
}

__device__ __forceinline__ float sigm(float x) {
  return __fdividef(1.0f, 1.0f + __expf(-x));
}
__device__ __forceinline__ float tanh_(float x) {
  float e = __expf(2.0f * x);
  return 1.0f - __fdividef(2.0f, e + 1.0f);
}

// strong (L2-coherent) 16B load: returns 2 records (h,tag,h,tag)
__device__ __forceinline__ uint4 ld_rec2(const uint2* p) {
  uint4 v;
  asm volatile("ld.relaxed.gpu.global.v4.b32 {%0,%1,%2,%3}, [%4];"
               : "=r"(v.x), "=r"(v.y), "=r"(v.z), "=r"(v.w) : "l"(p) : "memory");
  return v;
}
// strong 8B store: one record (h, tag) — tag travels with the payload
__device__ __forceinline__ void st_rec(uint2* p, float h, unsigned tag) {
  asm volatile("st.relaxed.gpu.global.v2.b32 [%0], {%1,%2};"
               :: "l"(p), "r"(__float_as_uint(h)), "r"(tag) : "memory");
}

// ==============================================================================
// Kernel 1: xg[m][n] = sum_k emb[inputs[m]][k] * W_ih[n][k] + b_ih[n] + b_hh[n]
// 128x128 tile, BK=8, 256 threads, 8x8 micro-tile via fma.rn.f32x2.
// DOUBLE-BUFFERED smem: one __syncthreads per K-tile (vs two) — 128 barriers
// instead of 256 — with next-tile global loads issued before the compute block.
// Also resets the scan h-records (stream-ordered before the scan).
// ==============================================================================
__global__ __launch_bounds__(256, 2) void xg_gemm(
    const int*   __restrict__ inputs,
    const float* __restrict__ emb,
    const float* __restrict__ Wih,
    const float* __restrict__ b_ih,
    const float* __restrict__ b_hh)
{
  if (blockIdx.x == 0 && blockIdx.y == 0) {
    for (int i = threadIdx.x; i < 2 * HID; i += 256)
      ((uint2*)g_hrec)[i] = make_uint2(0u, 0u);
  }

  __shared__ __align__(16) float As[2][8][128];
  __shared__ __align__(16) float Bs[2][8][128];
  __shared__ int idx[128];

  const int tid = threadIdx.x;
  const int m0 = blockIdx.y << 7;
  const int n0 = blockIdx.x << 7;

  if (tid < 128) idx[tid] = inputs[m0 + tid];
  __syncthreads();

  const int lr = tid >> 1;           // 0..127 row for cooperative loads
  const int lk = (tid & 1) << 2;     // k offset 0 or 4
  const int tx = tid & 15;           // micro-tile col group
  const int ty = tid >> 4;           // micro-tile row group

  const float* aptr = emb + (size_t)idx[lr] * 1024 + lk;
  const float* bptr = Wih + (size_t)(n0 + lr) * 1024 + lk;

  ull acc2[8][4];
  #pragma unroll
  for (int i = 0; i < 8; ++i)
    #pragma unroll
    for (int p = 0; p < 4; ++p) acc2[i][p] = 0ULL;

  // prologue: tile 0 -> buffer 0
  {
    float4 av = *(const float4*)(aptr);
    float4 bv = *(const float4*)(bptr);
    As[0][lk + 0][lr] = av.x; As[0][lk + 1][lr] = av.y;
    As[0][lk + 2][lr] = av.z; As[0][lk + 3][lr] = av.w;
    Bs[0][lk + 0][lr] = bv.x; Bs[0][lk + 1][lr] = bv.y;
    Bs[0][lk + 2][lr] = bv.z; Bs[0][lk + 3][lr] = bv.w;
  }
  __syncthreads();

  for (int t = 0; t < 128; ++t) {
    const int cur = t & 1;
    const int nxt = cur ^ 1;

    // issue next tile's global loads before compute (latency hidden under FMA)
    float4 av, bv;
    const bool has_next = (t + 1 < 128);
    if (has_next) {
      av = *(const float4*)(aptr + (t + 1) * 8);
      bv = *(const float4*)(bptr + (t + 1) * 8);
    }

    #pragma unroll
    for (int kk = 0; kk < 8; ++kk) {
      float4 a0 = *(const float4*)&As[cur][kk][ty << 3];
      float4 a1 = *(const float4*)&As[cur][kk][(ty << 3) + 4];
      float4 b0 = *(const float4*)&Bs[cur][kk][tx << 3];
      float4 b1 = *(const float4*)&Bs[cur][kk][(tx << 3) + 4];
      ull bq[4];
      bq[0] = pk2(b0.x, b0.y); bq[1] = pk2(b0.z, b0.w);
      bq[2] = pk2(b1.x, b1.y); bq[3] = pk2(b1.z, b1.w);
      float a[8] = {a0.x, a0.y, a0.z, a0.w, a1.x, a1.y, a1.z, a1.w};
      #pragma unroll
      for (int i = 0; i < 8; ++i) {
        ull ad = pk2(a[i], a[i]);
        #pragma unroll
        for (int p = 0; p < 4; ++p) fma2(acc2[i][p], ad, bq[p]);
      }
    }

    // stage next tile into the other buffer (read during t-1 by all warps,
    // per the barrier at the end of t-1 — safe to overwrite now)
    if (has_next) {
      As[nxt][lk + 0][lr] = av.x; As[nxt][lk + 1][lr] = av.y;
      As[nxt][lk + 2][lr] = av.z; As[nxt][lk + 3][lr] = av.w;
      Bs[nxt][lk + 0][lr] = bv.x; Bs[nxt][lk + 1][lr] = bv.y;
      Bs[nxt][lk + 2][lr] = bv.z; Bs[nxt][lk + 3][lr] = bv.w;
      __syncthreads();   // single barrier per tile
    }
  }

  float bias[8];
  #pragma unroll
  for (int p = 0; p < 8; ++p) {
    int n = n0 + (tx << 3) + p;
    bias[p] = b_ih[n] + b_hh[n];
  }
  #pragma unroll
  for (int i = 0; i < 8; ++i) {
    float c[8];
    #pragma unroll
    for (int p = 0; p < 4; ++p) upk2(acc2[i][p], c[2 * p], c[2 * p + 1]);
    #pragma unroll
    for (int p = 0; p < 8; ++p) c[p] += bias[p];
    int m = m0 + (ty << 3) + i;
    float* outp = g_xg + (size_t)m * G4 + n0 + (tx << 3);
    *(float4*)(outp)     = make_float4(c[0], c[1], c[2], c[3]);
    *(float4*)(outp + 4) = make_float4(c[4], c[5], c[6], c[7]);
  }
}

// ==============================================================================
// Kernel 2: persistent LSTM scan — byte-exact restore of the 6943us (R7)
// kernel. 128 CTAs x 256 threads; CTA b owns h columns [8b, 8b+8), warp w ->
// column j. Poll loop FROZEN: two serial do/while spins (every "smarter"
// variant regressed: merged re-issue +2.0ms, issue-ahead serial-verify +3.6ms,
// concurrent-verify +1.1ms). Tag+payload in one 8B record; publish per-warp;
// trailing barrier throttles next-step polling.
// ==============================================================================
__global__ __launch_bounds__(SCAN_THREADS, 1) void lstm_scan(
    const float* __restrict__ W_hh,
    const float* __restrict__ h0,
    const float* __restrict__ c0)
{
  const int tid  = threadIdx.x;
  const int lane = tid & 31;
  const int w    = tid >> 5;                  // warp 0..7
  const int j    = (blockIdx.x << 3) + w;     // 0..1023

  __shared__ __align__(16) float sh_h[HID];

  // load this thread's 128 weights (as 64 f32x2 pairs) into registers
  ull wreg[4][16];
  #pragma unroll
  for (int g = 0; g < 4; ++g) {
    const float* wp = W_hh + (size_t)(j + (g << 10)) * HID;
    #pragma unroll
    for (int i = 0; i < 16; ++i) {
      float2 v = *(const float2*)(wp + 2 * (lane + 32 * i));
      wreg[g][i] = pk2(v.x, v.y);
    }
  }
  float c = c0[j];   // replicated across lanes (identical updates keep it consistent)

  for (int t = 0; t < SEQ; ++t) {
    // prefetch this step's input-side gate values early (hides DRAM/L2 latency
    // behind the record wait)
    float xgv = 0.0f;
    if (lane < 4) xgv = __ldg(g_xg + (size_t)t * G4 + j + (lane << 10));

    // --- obtain h_t into shared memory ---
    if (t == 0) {
      ((float4*)sh_h)[tid] = ((const float4*)h0)[tid];
    } else {
      // thread tid owns records 4*tid .. 4*tid+3 (two 16B loads, coalesced).
      // A 16B strong load returns (h,tag,h,tag) atomically: once tags >= t,
      // the h payloads in the same load are the current step's values.
      const uint2* rp = &g_hrec[t & 1][tid << 2];
      const unsigned tt = (unsigned)t;
      uint4 a, b;
      do { a = ld_rec2(rp);     } while (a.y < tt || a.w < tt);
      do { b = ld_rec2(rp + 2); } while (b.y < tt || b.w < tt);
      ((float4*)sh_h)[tid] = make_float4(__uint_as_float(a.x), __uint_as_float(a.z),
                                         __uint_as_float(b.x), __uint_as_float(b.z));
    }
    __syncthreads();

    // --- 4 dot products of length 1024, f32x2 packed ---
    ull acc2[4];
    #pragma unroll
    for (int g = 0; g < 4; ++g) acc2[g] = 0ULL;
    #pragma unroll
    for (int i = 0; i < 16; ++i) {
      ull hh = *(const ull*)(sh_h + 2 * (lane + 32 * i));
      #pragma unroll
      for (int g = 0; g < 4; ++g) fma2(acc2[g], wreg[g][i], hh);
    }
    float acc[4];
    #pragma unroll
    for (int g = 0; g < 4; ++g) {
      float lo, hi; upk2(acc2[g], lo, hi);
      acc[g] = lo + hi;
    }
    // butterfly reduce: every lane ends with the full sums
    #pragma unroll
    for (int off = 16; off > 0; off >>= 1)
      #pragma unroll
      for (int g = 0; g < 4; ++g)
        acc[g] += __shfl_xor_sync(0xffffffffu, acc[g], off);

    float xg0 = __shfl_sync(0xffffffffu, xgv, 0);
    float xg1 = __shfl_sync(0xffffffffu, xgv, 1);
    float xg2 = __shfl_sync(0xffffffffu, xgv, 2);
    float xg3 = __shfl_sync(0xffffffffu, xgv, 3);

    // gate order i, f, g, o (PyTorch)
    float iv = sigm(acc[0] + xg0);
    float fv = sigm(acc[1] + xg1);
    float gv = tanh_(acc[2] + xg2);
    float ov = sigm(acc[3] + xg3);
    c = fv * c + iv * gv;
    float hn = ov * tanh_(c);

    // publish immediately — per-warp, no CTA-wide barrier on the publish path
    if (lane == 0)
      st_rec(&g_hrec[(t + 1) & 1][j], hn, (unsigned)(t + 1));

    // protect sh_h against next step's overwrite while other warps still read it
    __syncthreads();
  }
}

// ==============================================================================
// Kernel 3: log_softmax over the final hidden state. After step t=4095 the
// final h was published with tag 4096 into g_hrec[0]. One CTA, 1024 threads.
// ==============================================================================
__global__ void lsm_kernel(float* __restrict__ out)
{
  const int tid  = threadIdx.x;
  const int lane = tid & 31;
  const int w    = tid >> 5;
  __shared__ float red[32];
  __shared__ float bcast[2];

  float v = __uint_as_float(g_hrec[0][tid].x);

  float m = v;
  #pragma unroll
  for (int o = 16; o > 0; o >>= 1) m = fmaxf(m, __shfl_xor_sync(0xffffffffu, m, o));
  if (lane == 0) red[w] = m;
  __syncthreads();
  if (tid < 32) {
    float x = red[tid];
    #pragma unroll
    for (int o = 16; o > 0; o >>= 1) x = fmaxf(x, __shfl_xor_sync(0xffffffffu, x, o));
    if (tid == 0) bcast[0] = x;
  }
  __syncthreads();
  m = bcast[0];

  float e = __expf(v - m);
  float s = e;
  #pragma unroll
  for (int o = 16; o > 0; o >>= 1) s += __shfl_xor_sync(0xffffffffu, s, o);
  if (lane == 0) red[w] = s;
  __syncthreads();
  if (tid < 32) {
    float x = red[tid];
    #pragma unroll
    for (int o = 16; o > 0; o >>= 1) x += __shfl_xor_sync(0xffffffffu, x, o);
    if (tid == 0) bcast[1] = logf(x);
  }
  __syncthreads();

  out[tid] = (v - m) - bcast[1];
}

// ==============================================================================
extern "C" void kernel_launch(void* const* d_in, const int* in_sizes, int n_in,
                              void* d_out, int out_size)
{
  const int*   inputs = (const int*)  d_in[0];
  const float* emb    = (const float*)d_in[1];
  const float* W_ih   = (const float*)d_in[2];
  const float* W_hh   = (const float*)d_in[3];
  const float* b_ih   = (const float*)d_in[4];
  const float* b_hh   = (const float*)d_in[5];
  const float* h0     = (const float*)d_in[6];
  const float* c0     = (const float*)d_in[7];
  float* out = (float*)d_out;

  dim3 grid(G4 / 128, SEQ / 128);
  xg_gemm<<<grid, 256>>>(inputs, emb, W_ih, b_ih, b_hh);
  lstm_scan<<<NCTA, SCAN_THREADS>>>(W_hh, h0, c0);
  lsm_kernel<<<1, HID>>>(out);
}